// round 12
// baseline (speedup 1.0000x reference)
#include <cuda_runtime.h>
#include <cuda_fp16.h>
#include <cstdint>

#define H_  32
#define N_  2048
#define T_  2048
#define D_  128
#define R_  64

// Fragment-permuted fp16 operand buffers:
//   g_qA: [h*16 + nb][kt(4)][row(128)][lc(4)] uint4 — row = output n (identity)
//   g_kB: same shape, but token t stored at fragment row rho(t) so that the
//         MMA output fragment becomes 16B-contiguous in the output:
//         rho(t) = (2*(t>>4) + ((t>>1)&1))*8 + ((t>>2)&3)*2 + (t&1)
__device__ __align__(16) uint4 g_qA[H_ * 16 * 4 * 128 * 4];   // 16.8 MB
__device__ __align__(16) uint4 g_kB[H_ * 16 * 4 * 128 * 4];   // 16.8 MB

// ---------------------------------------------------------------------------
// packed f32x2 helpers (Blackwell sm_100+ family, NOT 'a'-gated)
// ---------------------------------------------------------------------------
__device__ __forceinline__ uint64_t pack2(float lo, float hi) {
    uint64_t v; asm("mov.b64 %0, {%1, %2};" : "=l"(v) : "f"(lo), "f"(hi)); return v;
}
__device__ __forceinline__ void unpack2(uint64_t v, float& lo, float& hi) {
    asm("mov.b64 {%0, %1}, %2;" : "=f"(lo), "=f"(hi) : "l"(v));
}
__device__ __forceinline__ uint64_t ffma2(uint64_t a, uint64_t b, uint64_t c) {
    uint64_t d;
    asm("fma.rn.f32x2 %0, %1, %2, %3;" : "=l"(d) : "l"(a), "l"(b), "l"(c));
    return d;
}

__device__ __forceinline__ uint32_t h2u(__half2 h) {
    union { __half2 h; uint32_t u; } c; c.h = h; return c.u;
}

__device__ __forceinline__ void mma_f16(float* c,
                                        uint32_t a0, uint32_t a1, uint32_t a2, uint32_t a3,
                                        uint32_t b0, uint32_t b1) {
    asm volatile(
        "mma.sync.aligned.m16n8k16.row.col.f32.f16.f16.f32 "
        "{%0,%1,%2,%3}, {%4,%5,%6,%7}, {%8,%9}, {%0,%1,%2,%3};\n"
        : "+f"(c[0]), "+f"(c[1]), "+f"(c[2]), "+f"(c[3])
        : "r"(a0), "r"(a1), "r"(a2), "r"(a3), "r"(b0), "r"(b1));
}

// ---------------------------------------------------------------------------
// Fused prep + qcvt kernel.
//   blocks [0, 1024): per (head, 64-token chunk):
//     stage 1 (exact fp32): s[t,r] = sign(sum_d e[t,d]*G[d,r]) -> s16 fp16
//     stage 2 (tensor core): corr = s @ G16^T  (m=64 t, n=128 d, k=64 r)
//                 keff[t,d] = fp16(kq + corr/64) -> rho-permuted g_kB
//   blocks [1024, 1280): q -> fp16 fragment-permute into g_qA (4 chunks each)
// ---------------------------------------------------------------------------
#define SG_S  68     // sG  [128][68] fp32 (d, r)
#define SE_S  65     // sE  [128][65] fp32 (d, t)
#define S16S  72     // s16 [64][72] halves (t, r)   — aliases sE region
#define G16S  72     // G16 [128][72] halves (d, r)
#define PREP_SMEM ((128 * SG_S + 128 * SE_S) * 4 + 128 * G16S * 2)

__global__ __launch_bounds__(256, 2) void qjl_prep_fused(
    const float* __restrict__ k_orig,
    const float* __restrict__ k_quant,
    const float* __restrict__ G,
    const float* __restrict__ q)
{
    // ---------------- qcvt part ----------------
    if (blockIdx.x >= 1024) {
        const int b2  = blockIdx.x - 1024;
        const int tid = threadIdx.x;
        #pragma unroll
        for (int it = 0; it < 4; it++) {
            int idx = (b2 * 4 + it) * 256 + tid;
            int row = idx & 127;
            int kt  = (idx >> 7) & 3;
            int hb  = idx >> 9;
            const float4* src = (const float4*)q + ((size_t)hb * 128 + row) * 32 + kt * 8;
            float4 r[8];
            #pragma unroll
            for (int j = 0; j < 8; j++) r[j] = src[j];
            const float* f = (const float*)r;
            uint4* dst = g_qA + ((size_t)hb * 4 + kt) * 512 + row * 4;
            #pragma unroll
            for (int lc = 0; lc < 4; lc++) {
                uint4 o;
                o.x = h2u(__floats2half2_rn(f[2*(lc     )], f[2*(lc     ) + 1]));
                o.y = h2u(__floats2half2_rn(f[2*(lc + 4 )], f[2*(lc + 4 ) + 1]));
                o.z = h2u(__floats2half2_rn(f[2*(lc + 8 )], f[2*(lc + 8 ) + 1]));
                o.w = h2u(__floats2half2_rn(f[2*(lc + 12)], f[2*(lc + 12) + 1]));
                dst[lc] = o;
            }
        }
        return;
    }

    // ---------------- prep part ----------------
    extern __shared__ float sm[];
    float*  sG  = sm;                                    // [128][SG_S] fp32
    float*  sE  = sG + 128 * SG_S;                       // [128][SE_S] fp32
    __half* G16 = (__half*)(sE + 128 * SE_S);            // [128][G16S] fp16
    uint32_t* s16w = (uint32_t*)sE;                      // s16 as u32, aliases sE
    const uint32_t* G16w = (const uint32_t*)G16;

    const int tid  = threadIdx.x;
    const int lane = tid & 31;
    const int wrp  = tid >> 5;
    const int h    = blockIdx.x & 31;
    const int t0   = (blockIdx.x >> 5) * 64;

    // load G (fp32 for stage 1, fp16 for stage 2)
    for (int i = tid; i < D_ * R_; i += 256) {
        int d = i >> 6, r = i & 63;
        float g = G[i];
        sG[d * SG_S + r] = g;
        G16[d * G16S + r] = __float2half_rn(g);
    }
    const float* ko = k_orig  + ((size_t)h * T_ + t0) * D_;
    const float* kq = k_quant + ((size_t)h * T_ + t0) * D_;
    for (int i = tid; i < 64 * D_; i += 256) {
        int t = i >> 7, d = i & 127;
        sE[d * SE_S + t] = ko[t * D_ + d] - kq[t * D_ + d];
    }
    __syncthreads();

    // ---- stage 1 (exact fp32): s = sign(e @ G), written as fp16 pairs to s16
    {
        const int tc = tid & 63;
        const int rg = tid >> 6;
        uint64_t acc[8];
        #pragma unroll
        for (int i = 0; i < 8; i++) acc[i] = pack2(0.f, 0.f);
        for (int d = 0; d < D_; d++) {
            float ev = sE[d * SE_S + tc];
            uint64_t ev2 = pack2(ev, ev);
            const ulonglong2* gp = (const ulonglong2*)(sG + d * SG_S + rg * 16);
            #pragma unroll
            for (int v = 0; v < 4; v++) {
                ulonglong2 g2 = gp[v];
                acc[v*2+0] = ffma2(ev2, g2.x, acc[v*2+0]);
                acc[v*2+1] = ffma2(ev2, g2.y, acc[v*2+1]);
            }
        }
        __syncthreads();   // all sE reads done before s16 (alias) writes
        #pragma unroll
        for (int i = 0; i < 8; i++) {
            float a0, a1;
            unpack2(acc[i], a0, a1);
            float s0 = (a0 > 0.f) ? 1.f : ((a0 < 0.f) ? -1.f : 0.f);
            float s1 = (a1 > 0.f) ? 1.f : ((a1 < 0.f) ? -1.f : 0.f);
            // s16[t = tc][r = rg*16 + 2i, 2i+1]  (u32 index: stride 36)
            s16w[tc * (S16S/2) + rg * 8 + i] = h2u(__floats2half2_rn(s0, s1));
        }
    }
    __syncthreads();

    // ---- stage 2 (tensor core): corr[t,d] = sum_r s16[t,r] * G16[d,r]
    // 8 warps: mw = wrp&3 -> t-tile mw*16 ; nw = wrp>>2 -> d-tile nw*64
    {
        const int mw = wrp & 3;
        const int nw = wrp >> 2;
        const int lg = lane >> 2;      // 0..7
        const int lc = lane & 3;       // 0..3

        float acc[8][4];
        #pragma unroll
        for (int nt = 0; nt < 8; nt++)
            #pragma unroll
            for (int v = 0; v < 4; v++) acc[nt][v] = 0.f;

        #pragma unroll
        for (int ks = 0; ks < 4; ks++) {
            const int t = mw * 16 + lg;
            uint32_t a0 = s16w[ t      * 36 + ks * 8 + lc];
            uint32_t a1 = s16w[(t + 8) * 36 + ks * 8 + lc];
            uint32_t a2 = s16w[ t      * 36 + ks * 8 + 4 + lc];
            uint32_t a3 = s16w[(t + 8) * 36 + ks * 8 + 4 + lc];
            #pragma unroll
            for (int nt = 0; nt < 8; nt++) {
                int n = nw * 64 + nt * 8 + lg;
                uint32_t b0 = G16w[n * 36 + ks * 8 + lc];
                uint32_t b1 = G16w[n * 36 + ks * 8 + 4 + lc];
                mma_f16(acc[nt], a0, a1, a2, a3, b0, b1);
            }
        }

        // epilogue: keff = fp16(kq + corr/64), u32 pair store into g_kB
        const int tb = (h << 4) + (t0 >> 7);
        const float scale = 1.f / 64.f;
        #pragma unroll
        for (int nt = 0; nt < 8; nt++) {
            int d0  = nw * 64 + nt * 8 + 2 * lc;
            int kt  = d0 >> 5;
            int wv  = (d0 >> 1) & 15;
            int lcq = wv & 3;
            int p   = wv >> 2;
            uint32_t* outp = (uint32_t*)g_kB + ((size_t)(tb * 4 + kt) * 128) * 16
                           + lcq * 4 + p;
            #pragma unroll
            for (int hh = 0; hh < 2; hh++) {
                int t_loc = mw * 16 + lg + hh * 8;
                float c0 = acc[nt][hh * 2 + 0];
                float c1 = acc[nt][hh * 2 + 1];
                float2 kq2 = *(const float2*)(kq + (size_t)t_loc * D_ + d0);
                int tl  = (t0 & 127) + t_loc;
                int row = (2 * (tl >> 4) + ((tl >> 1) & 1)) * 8
                        + ((tl >> 2) & 3) * 2 + (tl & 1);          // rho(tl)
                outp[row * 16] = h2u(__floats2half2_rn(kq2.x + c0 * scale,
                                                       kq2.y + c1 * scale));
            }
        }
    }
}

// ---------------------------------------------------------------------------
// Main GEMM, smem-free, barrier-free. Block tile 32x128, 8 warps (2x4),
// warp tile 16x32 -> ~56 live regs, 4 CTAs/SM (32 warps, 50% occ).
// B rows carry the rho() permutation -> STG.128 epilogue.
// ---------------------------------------------------------------------------
__global__ __launch_bounds__(256, 4) void qjl_gemm_kernel(float* __restrict__ out)
{
    const int tid  = threadIdx.x;
    const int warp = tid >> 5;
    const int lane = tid & 31;
    const int h  = blockIdx.z;
    const int nb = blockIdx.y;     // 0..63, 32 q-rows each
    const int tb = blockIdx.x;     // 0..15, 128 tokens each

    const uint4* __restrict__ Ab = g_qA + (size_t)((h << 4) + (nb >> 2)) * 2048;
    const uint4* __restrict__ Bb = g_kB + (size_t)((h << 4) + tb) * 2048;
    const int ro = (nb & 3) * 32;           // row offset within the 128-row A tile

    const int warp_m = (warp & 1) * 16;
    const int warp_n = (warp >> 1) * 32;
    const int lr = lane >> 2;
    const int lc = lane & 3;

    float acc[4][4];
    #pragma unroll
    for (int ni = 0; ni < 4; ni++)
        #pragma unroll
        for (int v = 0; v < 4; v++) acc[ni][v] = 0.f;

    #pragma unroll
    for (int kt = 0; kt < 4; kt++) {
        const uint4* Akt = Ab + kt * 512;
        const uint4* Bkt = Bb + kt * 512;

        // B fragments: one LDG.128 per ni covers both k8-steps
        uint4 bf[4];
        #pragma unroll
        for (int ni = 0; ni < 4; ni++)
            bf[ni] = Bkt[(warp_n + ni * 8 + lr) * 4 + lc];

        // A fragments (16 rows)
        int row = ro + warp_m + lr;
        uint4 alo = Akt[row * 4 + lc];
        uint4 ahi = Akt[(row + 8) * 4 + lc];

        #pragma unroll
        for (int ni = 0; ni < 4; ni++) {
            mma_f16(acc[ni], alo.x, ahi.x, alo.y, ahi.y, bf[ni].x, bf[ni].y);
            mma_f16(acc[ni], alo.z, ahi.z, alo.w, ahi.w, bf[ni].z, bf[ni].w);
        }
    }

    // epilogue: token-permuted fragments -> 16B-contiguous STG.128 per lane.
    float* Og = out + ((size_t)h * N_ + nb * 32) * T_ + tb * 128;
    {
        int row = warp_m + lr;
        #pragma unroll
        for (int j = 0; j < 2; j++) {
            int col = warp_n + 16 * j + 4 * lc;
            float4 v0 = make_float4(acc[2*j][0], acc[2*j][1],
                                    acc[2*j+1][0], acc[2*j+1][1]);
            float4 v1 = make_float4(acc[2*j][2], acc[2*j][3],
                                    acc[2*j+1][2], acc[2*j+1][3]);
            __stcs((float4*)(Og + (size_t)row * T_ + col), v0);
            __stcs((float4*)(Og + (size_t)(row + 8) * T_ + col), v1);
        }
    }
}

// ---------------------------------------------------------------------------
extern "C" void kernel_launch(void* const* d_in, const int* in_sizes, int n_in,
                              void* d_out, int out_size)
{
    const float* q  = (const float*)d_in[0];
    const float* ko = (const float*)d_in[1];
    const float* kq = (const float*)d_in[2];
    const float* G  = (const float*)d_in[3];
    float* out = (float*)d_out;

    cudaFuncSetAttribute(qjl_prep_fused, cudaFuncAttributeMaxDynamicSharedMemorySize,
                         (int)PREP_SMEM);

    qjl_prep_fused<<<1280, 256, PREP_SMEM>>>(ko, kq, G, q);
    qjl_gemm_kernel<<<dim3(T_ / 128, N_ / 32, H_), 256>>>(out);
}

// round 13
// speedup vs baseline: 1.0454x; 1.0454x over previous
#include <cuda_runtime.h>
#include <cuda_fp16.h>
#include <cstdint>

#define H_  32
#define N_  2048
#define T_  2048
#define D_  128
#define R_  64

// Fragment-permuted fp16 operand buffers:
//   g_qA: [h*16 + nb][kt(4)][row(128)][lc(4)] uint4 — row = output n (identity)
//   g_kB: same shape, but token t stored at fragment row rho(t) so that the
//         MMA output fragment becomes 16B-contiguous in the output:
//         rho(t) = (2*(t>>4) + ((t>>1)&1))*8 + ((t>>2)&3)*2 + (t&1)
__device__ __align__(16) uint4 g_qA[H_ * 16 * 4 * 128 * 4];   // 16.8 MB
__device__ __align__(16) uint4 g_kB[H_ * 16 * 4 * 128 * 4];   // 16.8 MB

// ---------------------------------------------------------------------------
// packed f32x2 helpers (Blackwell sm_100+ family, NOT 'a'-gated)
// ---------------------------------------------------------------------------
__device__ __forceinline__ uint64_t pack2(float lo, float hi) {
    uint64_t v; asm("mov.b64 %0, {%1, %2};" : "=l"(v) : "f"(lo), "f"(hi)); return v;
}
__device__ __forceinline__ void unpack2(uint64_t v, float& lo, float& hi) {
    asm("mov.b64 {%0, %1}, %2;" : "=f"(lo), "=f"(hi) : "l"(v));
}
__device__ __forceinline__ uint64_t ffma2(uint64_t a, uint64_t b, uint64_t c) {
    uint64_t d;
    asm("fma.rn.f32x2 %0, %1, %2, %3;" : "=l"(d) : "l"(a), "l"(b), "l"(c));
    return d;
}

__device__ __forceinline__ uint32_t h2u(__half2 h) {
    union { __half2 h; uint32_t u; } c; c.h = h; return c.u;
}

__device__ __forceinline__ void mma_f16(float* c,
                                        uint32_t a0, uint32_t a1, uint32_t a2, uint32_t a3,
                                        uint32_t b0, uint32_t b1) {
    asm volatile(
        "mma.sync.aligned.m16n8k16.row.col.f32.f16.f16.f32 "
        "{%0,%1,%2,%3}, {%4,%5,%6,%7}, {%8,%9}, {%0,%1,%2,%3};\n"
        : "+f"(c[0]), "+f"(c[1]), "+f"(c[2]), "+f"(c[3])
        : "r"(a0), "r"(a1), "r"(a2), "r"(a3), "r"(b0), "r"(b1));
}

// ---------------------------------------------------------------------------
// Fused prep + qcvt kernel, phase-overlaid smem (66.5 KB -> 3 CTAs/SM).
//   Phase 1 (exact fp32):  sG [128][68] f32, sE [128][65] f32
//       s[t,r] = sign(sum_d e[t,d]*G[d,r])
//   Phase 2 (tensor core): G16 [128][72] f16 (overlays sG),
//                          s16 [64][72] f16 (overlays sE tail)
//       corr = s @ G16^T ; keff = fp16(kq + corr/64) -> rho-permuted g_kB
//   blocks [1024,1280): q -> fp16 fragment-permute into g_qA
// ---------------------------------------------------------------------------
#define SG_S  68
#define SE_S  65
#define PREP_SMEM ((128 * SG_S + 128 * SE_S) * 4)     // 68096 B
#define S16O  10240     // u32 offset of s16 (byte 40960, inside sE region)

__global__ __launch_bounds__(256, 3) void qjl_prep_fused(
    const float* __restrict__ k_orig,
    const float* __restrict__ k_quant,
    const float* __restrict__ G,
    const float* __restrict__ q)
{
    // ---------------- qcvt part ----------------
    if (blockIdx.x >= 1024) {
        const int b2  = blockIdx.x - 1024;
        const int tid = threadIdx.x;
        #pragma unroll
        for (int it = 0; it < 4; it++) {
            int idx = (b2 * 4 + it) * 256 + tid;
            int row = idx & 127;
            int kt  = (idx >> 7) & 3;
            int hb  = idx >> 9;
            const float4* src = (const float4*)q + ((size_t)hb * 128 + row) * 32 + kt * 8;
            float4 r[8];
            #pragma unroll
            for (int j = 0; j < 8; j++) r[j] = src[j];
            const float* f = (const float*)r;
            uint4* dst = g_qA + ((size_t)hb * 4 + kt) * 512 + row * 4;
            #pragma unroll
            for (int lc = 0; lc < 4; lc++) {
                uint4 o;
                o.x = h2u(__floats2half2_rn(f[2*(lc     )], f[2*(lc     ) + 1]));
                o.y = h2u(__floats2half2_rn(f[2*(lc + 4 )], f[2*(lc + 4 ) + 1]));
                o.z = h2u(__floats2half2_rn(f[2*(lc + 8 )], f[2*(lc + 8 ) + 1]));
                o.w = h2u(__floats2half2_rn(f[2*(lc + 12)], f[2*(lc + 12) + 1]));
                dst[lc] = o;
            }
        }
        return;
    }

    // ---------------- prep part ----------------
    extern __shared__ float sm[];
    float*    sG   = sm;                         // [128][SG_S] f32 (phase 1)
    float*    sE   = sG + 128 * SG_S;            // [128][SE_S] f32 (phase 1)
    uint32_t* G16w = (uint32_t*)sm;              // [128][36] u32 (phase 2, overlays sG+)
    uint32_t* s16w = (uint32_t*)sm + S16O;       // [64][36] u32 (phase 2, overlays sE tail)

    const int tid  = threadIdx.x;
    const int lane = tid & 31;
    const int wrp  = tid >> 5;
    const int h    = blockIdx.x & 31;
    const int t0   = (blockIdx.x >> 5) * 64;

    for (int i = tid; i < D_ * R_; i += 256) {
        int d = i >> 6, r = i & 63;
        sG[d * SG_S + r] = G[i];
    }
    const float* ko = k_orig  + ((size_t)h * T_ + t0) * D_;
    const float* kq = k_quant + ((size_t)h * T_ + t0) * D_;
    for (int i = tid; i < 64 * D_; i += 256) {
        int t = i >> 7, d = i & 127;
        sE[d * SE_S + t] = ko[t * D_ + d] - kq[t * D_ + d];
    }
    __syncthreads();

    // ---- stage 1 (exact fp32): s = sign(e @ G)
    uint64_t acc1[8];
    {
        const int tc = tid & 63;
        const int rg = tid >> 6;
        #pragma unroll
        for (int i = 0; i < 8; i++) acc1[i] = pack2(0.f, 0.f);
        for (int d = 0; d < D_; d++) {
            float ev = sE[d * SE_S + tc];
            uint64_t ev2 = pack2(ev, ev);
            const ulonglong2* gp = (const ulonglong2*)(sG + d * SG_S + rg * 16);
            #pragma unroll
            for (int v = 0; v < 4; v++) {
                ulonglong2 g2 = gp[v];
                acc1[v*2+0] = ffma2(ev2, g2.x, acc1[v*2+0]);
                acc1[v*2+1] = ffma2(ev2, g2.y, acc1[v*2+1]);
            }
        }
    }
    // grab this thread's G chunk for the fp16 copy (reads sG; d = tid>>1)
    float greg[32];
    {
        const int d  = tid >> 1;
        const int r0 = (tid & 1) * 32;
        #pragma unroll
        for (int j = 0; j < 32; j++) greg[j] = sG[d * SG_S + r0 + j];
    }
    __syncthreads();   // all sG/sE reads done before phase-2 overlays

    // write s16 (overlays sE tail) — fp16 sign pairs
    {
        const int tc = tid & 63;
        const int rg = tid >> 6;
        #pragma unroll
        for (int i = 0; i < 8; i++) {
            float a0, a1;
            unpack2(acc1[i], a0, a1);
            float s0 = (a0 > 0.f) ? 1.f : ((a0 < 0.f) ? -1.f : 0.f);
            float s1 = (a1 > 0.f) ? 1.f : ((a1 < 0.f) ? -1.f : 0.f);
            s16w[tc * 36 + rg * 8 + i] = h2u(__floats2half2_rn(s0, s1));
        }
    }
    // write G16 (overlays sG region)
    {
        const int d  = tid >> 1;
        const int r0 = (tid & 1) * 32;
        #pragma unroll
        for (int j = 0; j < 16; j++)
            G16w[d * 36 + (r0 >> 1) + j] =
                h2u(__floats2half2_rn(greg[2*j], greg[2*j+1]));
    }
    __syncthreads();

    // ---- stage 2 (tensor core): corr[t,d] = sum_r s16[t,r] * G16[d,r]
    {
        const int mw = wrp & 3;
        const int nw = wrp >> 2;
        const int lg = lane >> 2;
        const int lc = lane & 3;

        float acc[8][4];
        #pragma unroll
        for (int nt = 0; nt < 8; nt++)
            #pragma unroll
            for (int v = 0; v < 4; v++) acc[nt][v] = 0.f;

        #pragma unroll
        for (int ks = 0; ks < 4; ks++) {
            const int t = mw * 16 + lg;
            uint32_t a0 = s16w[ t      * 36 + ks * 8 + lc];
            uint32_t a1 = s16w[(t + 8) * 36 + ks * 8 + lc];
            uint32_t a2 = s16w[ t      * 36 + ks * 8 + 4 + lc];
            uint32_t a3 = s16w[(t + 8) * 36 + ks * 8 + 4 + lc];
            #pragma unroll
            for (int nt = 0; nt < 8; nt++) {
                int n = nw * 64 + nt * 8 + lg;
                uint32_t b0 = G16w[n * 36 + ks * 8 + lc];
                uint32_t b1 = G16w[n * 36 + ks * 8 + 4 + lc];
                mma_f16(acc[nt], a0, a1, a2, a3, b0, b1);
            }
        }

        // epilogue: keff = fp16(kq + corr/64), u32 pair store into g_kB
        const int tb = (h << 4) + (t0 >> 7);
        const float scale = 1.f / 64.f;
        #pragma unroll
        for (int nt = 0; nt < 8; nt++) {
            int d0  = nw * 64 + nt * 8 + 2 * lc;
            int kt  = d0 >> 5;
            int wv  = (d0 >> 1) & 15;
            int lcq = wv & 3;
            int p   = wv >> 2;
            uint32_t* outp = (uint32_t*)g_kB + ((size_t)(tb * 4 + kt) * 128) * 16
                           + lcq * 4 + p;
            #pragma unroll
            for (int hh = 0; hh < 2; hh++) {
                int t_loc = mw * 16 + lg + hh * 8;
                float c0 = acc[nt][hh * 2 + 0];
                float c1 = acc[nt][hh * 2 + 1];
                float2 kq2 = *(const float2*)(kq + (size_t)t_loc * D_ + d0);
                int tl  = (t0 & 127) + t_loc;
                int row = (2 * (tl >> 4) + ((tl >> 1) & 1)) * 8
                        + ((tl >> 2) & 3) * 2 + (tl & 1);          // rho(tl)
                outp[row * 16] = h2u(__floats2half2_rn(kq2.x + c0 * scale,
                                                       kq2.y + c1 * scale));
            }
        }
    }
}

// ---------------------------------------------------------------------------
// Main GEMM (R11 config): smem-free, barrier-free. Block tile 64x128,
// 8 warps (2x4), warp tile 32x32, 3 CTAs/SM. rho() -> STG.128 epilogue.
// ---------------------------------------------------------------------------
__global__ __launch_bounds__(256, 3) void qjl_gemm_kernel(float* __restrict__ out)
{
    const int tid  = threadIdx.x;
    const int warp = tid >> 5;
    const int lane = tid & 31;
    const int h  = blockIdx.z;
    const int nb = blockIdx.y;     // 0..31, 64 q-rows each
    const int tb = blockIdx.x;     // 0..15, 128 tokens each

    const uint4* __restrict__ Ab = g_qA + (size_t)((h << 4) + (nb >> 1)) * 2048;
    const uint4* __restrict__ Bb = g_kB + (size_t)((h << 4) + tb) * 2048;
    const int ro = (nb & 1) * 64;

    const int warp_m = (warp & 1) * 32;
    const int warp_n = (warp >> 1) * 32;
    const int lr = lane >> 2;
    const int lc = lane & 3;

    float acc[2][4][4];
    #pragma unroll
    for (int mi = 0; mi < 2; mi++)
        #pragma unroll
        for (int ni = 0; ni < 4; ni++)
            #pragma unroll
            for (int v = 0; v < 4; v++) acc[mi][ni][v] = 0.f;

    #pragma unroll
    for (int kt = 0; kt < 4; kt++) {
        const uint4* Akt = Ab + kt * 512;
        const uint4* Bkt = Bb + kt * 512;

        uint4 bf[4];
        #pragma unroll
        for (int ni = 0; ni < 4; ni++)
            bf[ni] = Bkt[(warp_n + ni * 8 + lr) * 4 + lc];

        uint4 alo[2], ahi[2];
        #pragma unroll
        for (int mi = 0; mi < 2; mi++) {
            int row = ro + warp_m + mi * 16 + lr;
            alo[mi] = Akt[row * 4 + lc];
            ahi[mi] = Akt[(row + 8) * 4 + lc];
        }

        #pragma unroll
        for (int mi = 0; mi < 2; mi++)
            #pragma unroll
            for (int ni = 0; ni < 4; ni++) {
                mma_f16(acc[mi][ni], alo[mi].x, ahi[mi].x, alo[mi].y, ahi[mi].y,
                        bf[ni].x, bf[ni].y);
                mma_f16(acc[mi][ni], alo[mi].z, ahi[mi].z, alo[mi].w, ahi[mi].w,
                        bf[ni].z, bf[ni].w);
            }
    }

    float* Og = out + ((size_t)h * N_ + nb * 64) * T_ + tb * 128;
    #pragma unroll
    for (int mi = 0; mi < 2; mi++) {
        int row = warp_m + mi * 16 + lr;
        #pragma unroll
        for (int j = 0; j < 2; j++) {
            int col = warp_n + 16 * j + 4 * lc;
            float4 v0 = make_float4(acc[mi][2*j][0], acc[mi][2*j][1],
                                    acc[mi][2*j+1][0], acc[mi][2*j+1][1]);
            float4 v1 = make_float4(acc[mi][2*j][2], acc[mi][2*j][3],
                                    acc[mi][2*j+1][2], acc[mi][2*j+1][3]);
            __stcs((float4*)(Og + (size_t)row * T_ + col), v0);
            __stcs((float4*)(Og + (size_t)(row + 8) * T_ + col), v1);
        }
    }
}

// ---------------------------------------------------------------------------
extern "C" void kernel_launch(void* const* d_in, const int* in_sizes, int n_in,
                              void* d_out, int out_size)
{
    const float* q  = (const float*)d_in[0];
    const float* ko = (const float*)d_in[1];
    const float* kq = (const float*)d_in[2];
    const float* G  = (const float*)d_in[3];
    float* out = (float*)d_out;

    cudaFuncSetAttribute(qjl_prep_fused, cudaFuncAttributeMaxDynamicSharedMemorySize,
                         (int)PREP_SMEM);

    qjl_prep_fused<<<1280, 256, PREP_SMEM>>>(ko, kq, G, q);
    qjl_gemm_kernel<<<dim3(T_ / 128, N_ / 64, H_), 256>>>(out);
}